// round 1
// baseline (speedup 1.0000x reference)
#include <cuda_runtime.h>
#include <math.h>

// Problem constants
#define BATCH 4
#define SEQ   4096
#define DMODEL 512
#define PROJD  512
#define SCALE_QK 0.125f   // 1/sqrt(64)

// ---------------------------------------------------------------------------
// Scratch (device globals; allocation inside kernel_launch is forbidden)
// ---------------------------------------------------------------------------
__device__ float g_qp [BATCH * SEQ * PROJD];                 // 32 MB
__device__ float g_kp [BATCH * SEQ * PROJD];                 // 32 MB
__device__ float g_vp [BATCH * SEQ * PROJD];                 // 32 MB
__device__ float g_dpa[BATCH * SEQ * PROJD];                 // 32 MB
__device__ float g_S  [(size_t)BATCH * SEQ * SEQ];           // 256 MB

// ---------------------------------------------------------------------------
// Packed f32x2 helpers (Blackwell sm_103a)
// ---------------------------------------------------------------------------
__device__ __forceinline__ void fma2(unsigned long long& c,
                                     unsigned long long a,
                                     unsigned long long b) {
    asm("fma.rn.f32x2 %0, %1, %2, %3;" : "=l"(c) : "l"(a), "l"(b), "l"(c));
}
__device__ __forceinline__ unsigned long long pack_dup(float x) {
    unsigned long long p;
    unsigned int u = __float_as_uint(x);
    asm("mov.b64 %0, {%1, %2};" : "=l"(p) : "r"(u), "r"(u));
    return p;
}
__device__ __forceinline__ void unpack2(unsigned long long p, float& lo, float& hi) {
    unsigned int a, b;
    asm("mov.b64 {%0, %1}, %2;" : "=r"(a), "=r"(b) : "l"(p));
    lo = __uint_as_float(a);
    hi = __uint_as_float(b);
}

// ---------------------------------------------------------------------------
// GEMM: C[M,N] = scale * (A[M,K] @ op(B)) + bias[N]
//   TRANSB=false: B is [K,N] row-major;  TRANSB=true: B is [N,K] row-major.
// Tiles: 128x128x16, 256 threads, 8x8 per thread, f32x2 inner product.
// All dims assumed multiples of 128 (true for this problem; K mult of 16).
// blockIdx.z = batch, with per-operand batch strides.
// ---------------------------------------------------------------------------
template <bool TRANSB>
__global__ __launch_bounds__(256, 2)
void gemm_kernel(const float* __restrict__ A, const float* __restrict__ Bm,
                 float* __restrict__ C, const float* __restrict__ bias,
                 float scale, int M, int N, int K,
                 long long strideA, long long strideB, long long strideC)
{
    __shared__ float As[128 * 16];   // [row][k] row-major
    __shared__ float Bs[16 * 128];   // [k][n]  row-major

    const int tid = threadIdx.x;
    const int tx = tid & 15;         // n sub-tile
    const int ty = tid >> 4;         // m sub-tile
    const int m0 = blockIdx.y * 128;
    const int n0 = blockIdx.x * 128;

    A  += (long long)blockIdx.z * strideA;
    Bm += (long long)blockIdx.z * strideB;
    C  += (long long)blockIdx.z * strideC;

    unsigned long long acc[8][4];
    #pragma unroll
    for (int i = 0; i < 8; i++)
        #pragma unroll
        for (int j = 0; j < 4; j++) acc[i][j] = 0ull;

    for (int k0 = 0; k0 < K; k0 += 16) {
        // ---- load A tile: 128x16 = 512 float4, 2 per thread (coalesced) ----
        #pragma unroll
        for (int l = 0; l < 2; l++) {
            int idx = tid + l * 256;
            int row = idx >> 2, kq = idx & 3;
            float4 t = *(const float4*)(A + (long long)(m0 + row) * K + k0 + kq * 4);
            *(float4*)(As + idx * 4) = t;   // As[row][kq*4..] — linear, conflict-free
        }
        // ---- load B tile into Bs[k][n] ----
        if (!TRANSB) {
            #pragma unroll
            for (int l = 0; l < 2; l++) {
                int idx = tid + l * 256;
                int kk = idx >> 5, nq = idx & 31;
                float4 t = *(const float4*)(Bm + (long long)(k0 + kk) * N + n0 + nq * 4);
                *(float4*)(Bs + idx * 4) = t;
            }
        } else {
            #pragma unroll
            for (int l = 0; l < 2; l++) {
                int idx = tid + l * 256;
                int nrow = idx >> 2, kq = idx & 3;
                float4 t = *(const float4*)(Bm + (long long)(n0 + nrow) * K + k0 + kq * 4);
                Bs[(kq * 4 + 0) * 128 + nrow] = t.x;
                Bs[(kq * 4 + 1) * 128 + nrow] = t.y;
                Bs[(kq * 4 + 2) * 128 + nrow] = t.z;
                Bs[(kq * 4 + 3) * 128 + nrow] = t.w;
            }
        }
        __syncthreads();

        // ---- compute ----
        #pragma unroll
        for (int kk = 0; kk < 16; kk++) {
            // b fragment: 8 consecutive floats = 4 packed f32x2
            const unsigned long long* bp =
                (const unsigned long long*)(Bs + kk * 128 + tx * 8);
            unsigned long long b2[4];
            b2[0] = bp[0]; b2[1] = bp[1]; b2[2] = bp[2]; b2[3] = bp[3];

            #pragma unroll
            for (int i = 0; i < 8; i++) {
                unsigned long long a2 = pack_dup(As[(ty * 8 + i) * 16 + kk]);
                fma2(acc[i][0], a2, b2[0]);
                fma2(acc[i][1], a2, b2[1]);
                fma2(acc[i][2], a2, b2[2]);
                fma2(acc[i][3], a2, b2[3]);
            }
        }
        __syncthreads();
    }

    // ---- epilogue: scale + bias, vectorized store ----
    float bv[8];
    #pragma unroll
    for (int j = 0; j < 8; j++)
        bv[j] = bias ? bias[n0 + tx * 8 + j] : 0.0f;

    #pragma unroll
    for (int i = 0; i < 8; i++) {
        float out[8];
        #pragma unroll
        for (int j = 0; j < 4; j++) {
            float lo, hi;
            unpack2(acc[i][j], lo, hi);
            out[2 * j]     = lo * scale + bv[2 * j];
            out[2 * j + 1] = hi * scale + bv[2 * j + 1];
        }
        float* crow = C + (long long)(m0 + ty * 8 + i) * N + n0 + tx * 8;
        *(float4*)(crow)     = make_float4(out[0], out[1], out[2], out[3]);
        *(float4*)(crow + 4) = make_float4(out[4], out[5], out[6], out[7]);
    }
}

// ---------------------------------------------------------------------------
// Row softmax over 4096-wide rows. One block per row, 256 threads,
// 4 float4 per thread held in registers (single read + single write of S).
// ---------------------------------------------------------------------------
__global__ __launch_bounds__(256)
void softmax_kernel(float* __restrict__ S)
{
    const int row = blockIdx.x;
    float4* p4 = (float4*)(S + (size_t)row * SEQ);
    const int tid = threadIdx.x;

    float4 v[4];
    float m = -1e30f;
    #pragma unroll
    for (int i = 0; i < 4; i++) {
        v[i] = p4[tid + i * 256];
        m = fmaxf(m, fmaxf(fmaxf(v[i].x, v[i].y), fmaxf(v[i].z, v[i].w)));
    }

    __shared__ float red[8];
    // warp max
    #pragma unroll
    for (int o = 16; o > 0; o >>= 1) m = fmaxf(m, __shfl_xor_sync(0xffffffffu, m, o));
    if ((tid & 31) == 0) red[tid >> 5] = m;
    __syncthreads();
    if (tid == 0) {
        float t = red[0];
        #pragma unroll
        for (int w = 1; w < 8; w++) t = fmaxf(t, red[w]);
        red[0] = t;
    }
    __syncthreads();
    m = red[0];
    __syncthreads();   // protect red[] reuse for the sum

    float s = 0.0f;
    #pragma unroll
    for (int i = 0; i < 4; i++) {
        v[i].x = __expf(v[i].x - m);  s += v[i].x;
        v[i].y = __expf(v[i].y - m);  s += v[i].y;
        v[i].z = __expf(v[i].z - m);  s += v[i].z;
        v[i].w = __expf(v[i].w - m);  s += v[i].w;
    }
    #pragma unroll
    for (int o = 16; o > 0; o >>= 1) s += __shfl_xor_sync(0xffffffffu, s, o);
    if ((tid & 31) == 0) red[tid >> 5] = s;
    __syncthreads();
    if (tid == 0) {
        float t = 0.0f;
        #pragma unroll
        for (int w = 0; w < 8; w++) t += red[w];
        red[0] = t;
    }
    __syncthreads();
    const float inv = 1.0f / red[0];

    #pragma unroll
    for (int i = 0; i < 4; i++) {
        v[i].x *= inv; v[i].y *= inv; v[i].z *= inv; v[i].w *= inv;
        p4[tid + i * 256] = v[i];
    }
}

// ---------------------------------------------------------------------------
// Launch
// ---------------------------------------------------------------------------
extern "C" void kernel_launch(void* const* d_in, const int* in_sizes, int n_in,
                              void* d_out, int out_size)
{
    const float* q     = (const float*)d_in[0];
    const float* k     = (const float*)d_in[1];
    const float* v     = (const float*)d_in[2];
    const float* w_q   = (const float*)d_in[3];
    const float* w_k   = (const float*)d_in[4];
    const float* w_v   = (const float*)d_in[5];
    const float* w_mha = (const float*)d_in[6];
    const float* b_q   = (const float*)d_in[7];
    const float* b_k   = (const float*)d_in[8];
    const float* b_v   = (const float*)d_in[9];
    const float* b_mha = (const float*)d_in[10];
    float* out = (float*)d_out;

    float *qp, *kp, *vp, *dpa, *S;
    cudaGetSymbolAddress((void**)&qp,  g_qp);
    cudaGetSymbolAddress((void**)&kp,  g_kp);
    cudaGetSymbolAddress((void**)&vp,  g_vp);
    cudaGetSymbolAddress((void**)&dpa, g_dpa);
    cudaGetSymbolAddress((void**)&S,   g_S);

    const int MFLAT = BATCH * SEQ;                 // 16384
    const long long sP = (long long)SEQ * PROJD;   // per-batch stride, projections
    const long long sS = (long long)SEQ * SEQ;     // per-batch stride, scores

    dim3 blk(256);

    // 1) Projections: [16384,512] @ [512,512] + bias
    {
        dim3 grd(PROJD / 128, MFLAT / 128, 1);
        gemm_kernel<false><<<grd, blk>>>(q, w_q, qp, b_q, 1.0f,
                                         MFLAT, PROJD, DMODEL, 0, 0, 0);
        gemm_kernel<false><<<grd, blk>>>(k, w_k, kp, b_k, 1.0f,
                                         MFLAT, PROJD, DMODEL, 0, 0, 0);
        gemm_kernel<false><<<grd, blk>>>(v, w_v, vp, b_v, 1.0f,
                                         MFLAT, PROJD, DMODEL, 0, 0, 0);
    }

    // 2) Scores: S_b = (qp_b @ kp_b^T) * 0.125   [4096,4096], batched
    {
        dim3 grd(SEQ / 128, SEQ / 128, BATCH);
        gemm_kernel<true><<<grd, blk>>>(qp, kp, S, nullptr, SCALE_QK,
                                        SEQ, SEQ, PROJD, sP, sP, sS);
    }

    // 3) Row softmax over 4096-wide rows
    softmax_kernel<<<BATCH * SEQ, blk>>>(S);

    // 4) dpa_b = P_b @ vp_b   [4096,512] = [4096,4096] @ [4096,512], batched
    {
        dim3 grd(PROJD / 128, SEQ / 128, BATCH);
        gemm_kernel<false><<<grd, blk>>>(S, vp, dpa, nullptr, 1.0f,
                                         SEQ, PROJD, SEQ, sS, sP, sP);
    }

    // 5) out = dpa @ w_mha + b_mha   [16384,512]
    {
        dim3 grd(DMODEL / 128, MFLAT / 128, 1);
        gemm_kernel<false><<<grd, blk>>>(dpa, w_mha, out, b_mha, 1.0f,
                                         MFLAT, DMODEL, PROJD, 0, 0, 0);
    }
}

// round 4
// speedup vs baseline: 1.9413x; 1.9413x over previous
#include <cuda_runtime.h>
#include <cuda_fp16.h>
#include <cstdint>
#include <math.h>

// ---------------------------------------------------------------------------
// Problem constants
// ---------------------------------------------------------------------------
#define BATCH 4
#define SEQ   4096
#define DMODEL 512
#define PROJD  512
#define MFLAT (BATCH * SEQ)
#define SCALE_QK 0.125f   // 1/sqrt(64)

// ---------------------------------------------------------------------------
// Scratch (device globals; no allocation allowed)
// ---------------------------------------------------------------------------
__device__ float g_qp [MFLAT * PROJD];                  // 32 MB
__device__ float g_kp [MFLAT * PROJD];                  // 32 MB
__device__ float g_vp [MFLAT * PROJD];                  // 32 MB
__device__ float g_vpT[MFLAT * PROJD];                  // 32 MB (per-batch [512,4096])
__device__ float g_dpa[MFLAT * PROJD];                  // 32 MB
__device__ float g_S  [(size_t)BATCH * SEQ * SEQ];      // 256 MB
__device__ float g_wqT[DMODEL * PROJD];
__device__ float g_wkT[DMODEL * PROJD];
__device__ float g_wvT[DMODEL * PROJD];
__device__ float g_wmT[PROJD * DMODEL];

// ---------------------------------------------------------------------------
// fp16 two-term split helpers
// ---------------------------------------------------------------------------
__device__ __forceinline__ void split2(float x, float y, uint32_t& hi, uint32_t& lo) {
    __half2 h = __floats2half2_rn(x, y);
    float2  f = __half22float2(h);
    __half2 l = __floats2half2_rn(x - f.x, y - f.y);
    hi = *(uint32_t*)&h;
    lo = *(uint32_t*)&l;
}

// m16n8k16 fp16 MMA, fp32 accumulate (baseline PTX, sm_80+)
__device__ __forceinline__ void mma_f16(float* d, const uint32_t* a, const uint32_t* b) {
    asm volatile(
        "mma.sync.aligned.m16n8k16.row.col.f32.f16.f16.f32 "
        "{%0,%1,%2,%3}, {%4,%5,%6,%7}, {%8,%9}, {%0,%1,%2,%3};\n"
        : "+f"(d[0]), "+f"(d[1]), "+f"(d[2]), "+f"(d[3])
        : "r"(a[0]), "r"(a[1]), "r"(a[2]), "r"(a[3]),
          "r"(b[0]), "r"(b[1]));
}

// ---------------------------------------------------------------------------
// fp16x3 tensor-core GEMM:  C[M,N] = scale * (A[M,K] @ B^T) + bias[N]
//   A: [M,K] row-major.  B: [N,K] row-major.  Dims mult of 128, K mult of 32.
//   CTA tile 128x128, BK=32, 8 warps (4M x 2N), warp tile 32x64.
//   Each fp32 split into hi/lo fp16; acc += hi*hi + hi*lo + lo*hi.
//   SMEM row: [hi k0-15 | lo k0-15 | hi k16-31 | lo k16-31] = 32 words, pitch 36.
//   Double buffered; LDG->split->STS staging with register prefetch.
// ---------------------------------------------------------------------------
#define BK 32
#define WPR 36                       // words per row
#define STAGE_WORDS (128 * WPR)      // per matrix per stage
#define SMEM_BYTES (2 * 2 * STAGE_WORDS * 4)   // 2 stages x (A+B) = 73728 B

__global__ void __launch_bounds__(256)
gemm_mma(const float* __restrict__ A, const float* __restrict__ Bm,
         float* __restrict__ C, const float* __restrict__ bias,
         float scale, int K, int ldC,
         long long sA, long long sB, long long sC)
{
    extern __shared__ uint32_t sw[];
    // layout: stage0 A | stage0 B | stage1 A | stage1 B
    const int tid   = threadIdx.x;
    const int wid   = tid >> 5;
    const int lane  = tid & 31;
    const int g     = lane >> 2;        // 0..7
    const int tg    = lane & 3;         // 0..3
    const int wm    = wid & 3;          // warp M (0..3)
    const int wn    = wid >> 2;         // warp N (0..1)
    const long long m0 = (long long)blockIdx.y * 128;
    const long long n0 = (long long)blockIdx.x * 128;

    A  += (long long)blockIdx.z * sA;
    Bm += (long long)blockIdx.z * sB;
    C  += (long long)blockIdx.z * sC;

    const float* Abase = A  + m0 * K;
    const float* Bbase = Bm + n0 * K;

    // global-load coords: 128 rows x 8 float4 = 1024 float4 per matrix; 4/thread
    int lr[4], lq[4];
    #pragma unroll
    for (int i = 0; i < 4; i++) {
        int f = tid + i * 256;
        lr[i] = f >> 3;
        lq[i] = f & 7;
    }

    float acc[2][8][4];
    #pragma unroll
    for (int i = 0; i < 2; i++)
        #pragma unroll
        for (int j = 0; j < 8; j++)
            #pragma unroll
            for (int l = 0; l < 4; l++) acc[i][j][l] = 0.0f;

    float4 pa[4], pb[4];
    #pragma unroll
    for (int i = 0; i < 4; i++) {
        pa[i] = *(const float4*)(Abase + (long long)lr[i] * K + lq[i] * 4);
        pb[i] = *(const float4*)(Bbase + (long long)lr[i] * K + lq[i] * 4);
    }

    // store chunk 0 into stage 0
    {
        uint32_t* as = sw;
        uint32_t* bs = sw + STAGE_WORDS;
        #pragma unroll
        for (int i = 0; i < 4; i++) {
            uint32_t h0, l0, h1, l1;
            uint32_t* p;
            split2(pa[i].x, pa[i].y, h0, l0);
            split2(pa[i].z, pa[i].w, h1, l1);
            p = as + lr[i] * WPR + (lq[i] >> 2) * 16 + (lq[i] & 3) * 2;
            p[0] = h0; p[1] = h1; p[8] = l0; p[9] = l1;
            split2(pb[i].x, pb[i].y, h0, l0);
            split2(pb[i].z, pb[i].w, h1, l1);
            p = bs + lr[i] * WPR + (lq[i] >> 2) * 16 + (lq[i] & 3) * 2;
            p[0] = h0; p[1] = h1; p[8] = l0; p[9] = l1;
        }
    }
    __syncthreads();

    const int nch = K / BK;
    #pragma unroll 1
    for (int c = 0; c < nch; c++) {
        const int cur = c & 1;
        const uint32_t* as = sw + cur * 2 * STAGE_WORDS;
        const uint32_t* bs = as + STAGE_WORDS;

        // prefetch next chunk
        if (c + 1 < nch) {
            const float* Ap = Abase + (c + 1) * BK;
            const float* Bp = Bbase + (c + 1) * BK;
            #pragma unroll
            for (int i = 0; i < 4; i++) {
                pa[i] = *(const float4*)(Ap + (long long)lr[i] * K + lq[i] * 4);
                pb[i] = *(const float4*)(Bp + (long long)lr[i] * K + lq[i] * 4);
            }
        }

        // ---- compute: 2 k-steps of 16 ----
        #pragma unroll
        for (int ks = 0; ks < 2; ks++) {
            const int kb = ks * 16;
            uint32_t ah[2][4], al[2][4];
            #pragma unroll
            for (int mt = 0; mt < 2; mt++) {
                const int row = wm * 32 + mt * 16 + g;
                const uint32_t* ap = &as[row * WPR + kb];
                ah[mt][0] = ap[tg];
                ah[mt][1] = ap[8 * WPR + tg];
                ah[mt][2] = ap[tg + 4];
                ah[mt][3] = ap[8 * WPR + tg + 4];
                al[mt][0] = ap[tg + 8];
                al[mt][1] = ap[8 * WPR + tg + 8];
                al[mt][2] = ap[tg + 12];
                al[mt][3] = ap[8 * WPR + tg + 12];
            }
            #pragma unroll
            for (int nt = 0; nt < 8; nt++) {
                const int nrow = wn * 64 + nt * 8 + g;
                const uint32_t* bp = &bs[nrow * WPR + kb];
                uint32_t bh[2], bl[2];
                bh[0] = bp[tg];
                bh[1] = bp[tg + 4];
                bl[0] = bp[tg + 8];
                bl[1] = bp[tg + 12];
                mma_f16(acc[0][nt], ah[0], bh);
                mma_f16(acc[1][nt], ah[1], bh);
                mma_f16(acc[0][nt], ah[0], bl);
                mma_f16(acc[1][nt], ah[1], bl);
                mma_f16(acc[0][nt], al[0], bh);
                mma_f16(acc[1][nt], al[1], bh);
            }
        }

        // ---- publish next stage ----
        if (c + 1 < nch) {
            uint32_t* an = sw + (cur ^ 1) * 2 * STAGE_WORDS;
            uint32_t* bn = an + STAGE_WORDS;
            #pragma unroll
            for (int i = 0; i < 4; i++) {
                uint32_t h0, l0, h1, l1;
                uint32_t* p;
                split2(pa[i].x, pa[i].y, h0, l0);
                split2(pa[i].z, pa[i].w, h1, l1);
                p = an + lr[i] * WPR + (lq[i] >> 2) * 16 + (lq[i] & 3) * 2;
                p[0] = h0; p[1] = h1; p[8] = l0; p[9] = l1;
                split2(pb[i].x, pb[i].y, h0, l0);
                split2(pb[i].z, pb[i].w, h1, l1);
                p = bn + lr[i] * WPR + (lq[i] >> 2) * 16 + (lq[i] & 3) * 2;
                p[0] = h0; p[1] = h1; p[8] = l0; p[9] = l1;
            }
        }
        __syncthreads();
    }

    // ---- epilogue: scale + bias ----
    #pragma unroll
    for (int nt = 0; nt < 8; nt++) {
        const long long ccol = n0 + wn * 64 + nt * 8 + tg * 2;
        float b0v = 0.0f, b1v = 0.0f;
        if (bias) { b0v = bias[ccol]; b1v = bias[ccol + 1]; }
        #pragma unroll
        for (int mt = 0; mt < 2; mt++) {
            const long long rA = m0 + wm * 32 + mt * 16 + g;
            const long long rB = rA + 8;
            float2 o0, o1;
            o0.x = acc[mt][nt][0] * scale + b0v;
            o0.y = acc[mt][nt][1] * scale + b1v;
            o1.x = acc[mt][nt][2] * scale + b0v;
            o1.y = acc[mt][nt][3] * scale + b1v;
            *(float2*)(C + rA * ldC + ccol) = o0;
            *(float2*)(C + rB * ldC + ccol) = o1;
        }
    }
}

// ---------------------------------------------------------------------------
// Tiled transpose: out[c][r] = in[r][c].
// ---------------------------------------------------------------------------
__global__ __launch_bounds__(256)
void transpose_kernel(const float* __restrict__ in, float* __restrict__ out,
                      int rows, int cols, long long sIn, long long sOut)
{
    __shared__ float t[32][33];
    in  += (long long)blockIdx.z * sIn;
    out += (long long)blockIdx.z * sOut;
    const int tx = threadIdx.x, ty = threadIdx.y;
    const int c0 = blockIdx.x * 32, r0 = blockIdx.y * 32;
    #pragma unroll
    for (int i = ty; i < 32; i += 8)
        t[i][tx] = in[(long long)(r0 + i) * cols + c0 + tx];
    __syncthreads();
    #pragma unroll
    for (int i = ty; i < 32; i += 8)
        out[(long long)(c0 + i) * rows + r0 + tx] = t[tx][i];
}

// ---------------------------------------------------------------------------
// Row softmax over 4096-wide rows
// ---------------------------------------------------------------------------
__global__ __launch_bounds__(256)
void softmax_kernel(float* __restrict__ S)
{
    const int row = blockIdx.x;
    float4* p4 = (float4*)(S + (size_t)row * SEQ);
    const int tid = threadIdx.x;

    float4 v[4];
    float m = -1e30f;
    #pragma unroll
    for (int i = 0; i < 4; i++) {
        v[i] = p4[tid + i * 256];
        m = fmaxf(m, fmaxf(fmaxf(v[i].x, v[i].y), fmaxf(v[i].z, v[i].w)));
    }

    __shared__ float red[8];
    #pragma unroll
    for (int o = 16; o > 0; o >>= 1) m = fmaxf(m, __shfl_xor_sync(0xffffffffu, m, o));
    if ((tid & 31) == 0) red[tid >> 5] = m;
    __syncthreads();
    if (tid == 0) {
        float t = red[0];
        #pragma unroll
        for (int w = 1; w < 8; w++) t = fmaxf(t, red[w]);
        red[0] = t;
    }
    __syncthreads();
    m = red[0];
    __syncthreads();

    float s = 0.0f;
    #pragma unroll
    for (int i = 0; i < 4; i++) {
        v[i].x = __expf(v[i].x - m);  s += v[i].x;
        v[i].y = __expf(v[i].y - m);  s += v[i].y;
        v[i].z = __expf(v[i].z - m);  s += v[i].z;
        v[i].w = __expf(v[i].w - m);  s += v[i].w;
    }
    #pragma unroll
    for (int o = 16; o > 0; o >>= 1) s += __shfl_xor_sync(0xffffffffu, s, o);
    if ((tid & 31) == 0) red[tid >> 5] = s;
    __syncthreads();
    if (tid == 0) {
        float t = 0.0f;
        #pragma unroll
        for (int w = 0; w < 8; w++) t += red[w];
        red[0] = t;
    }
    __syncthreads();
    const float inv = 1.0f / red[0];

    #pragma unroll
    for (int i = 0; i < 4; i++) {
        v[i].x *= inv; v[i].y *= inv; v[i].z *= inv; v[i].w *= inv;
        p4[tid + i * 256] = v[i];
    }
}

// ---------------------------------------------------------------------------
// Launch
// ---------------------------------------------------------------------------
extern "C" void kernel_launch(void* const* d_in, const int* in_sizes, int n_in,
                              void* d_out, int out_size)
{
    const float* q     = (const float*)d_in[0];
    const float* k     = (const float*)d_in[1];
    const float* v     = (const float*)d_in[2];
    const float* w_q   = (const float*)d_in[3];
    const float* w_k   = (const float*)d_in[4];
    const float* w_v   = (const float*)d_in[5];
    const float* w_mha = (const float*)d_in[6];
    const float* b_q   = (const float*)d_in[7];
    const float* b_k   = (const float*)d_in[8];
    const float* b_v   = (const float*)d_in[9];
    const float* b_mha = (const float*)d_in[10];
    float* out = (float*)d_out;

    float *qp, *kp, *vp, *vpT, *dpa, *S, *wqT, *wkT, *wvT, *wmT;
    cudaGetSymbolAddress((void**)&qp,  g_qp);
    cudaGetSymbolAddress((void**)&kp,  g_kp);
    cudaGetSymbolAddress((void**)&vp,  g_vp);
    cudaGetSymbolAddress((void**)&vpT, g_vpT);
    cudaGetSymbolAddress((void**)&dpa, g_dpa);
    cudaGetSymbolAddress((void**)&S,   g_S);
    cudaGetSymbolAddress((void**)&wqT, g_wqT);
    cudaGetSymbolAddress((void**)&wkT, g_wkT);
    cudaGetSymbolAddress((void**)&wvT, g_wvT);
    cudaGetSymbolAddress((void**)&wmT, g_wmT);

    const long long sP = (long long)SEQ * PROJD;
    const long long sS = (long long)SEQ * SEQ;

    cudaFuncSetAttribute(gemm_mma, cudaFuncAttributeMaxDynamicSharedMemorySize, SMEM_BYTES);

    dim3 tblk(32, 8);
    dim3 blk(256);

    // 0) Transpose weights [K,N] -> [N,K]
    transpose_kernel<<<dim3(16, 16, 1), tblk>>>(w_q,   wqT, DMODEL, PROJD, 0, 0);
    transpose_kernel<<<dim3(16, 16, 1), tblk>>>(w_k,   wkT, DMODEL, PROJD, 0, 0);
    transpose_kernel<<<dim3(16, 16, 1), tblk>>>(w_v,   wvT, DMODEL, PROJD, 0, 0);
    transpose_kernel<<<dim3(16, 16, 1), tblk>>>(w_mha, wmT, PROJD, DMODEL, 0, 0);

    // 1) Projections: [16384,512] = A @ wT^T + bias
    {
        dim3 grd(PROJD / 128, MFLAT / 128, 1);
        gemm_mma<<<grd, blk, SMEM_BYTES>>>(q, wqT, qp, b_q, 1.0f, DMODEL, PROJD, 0, 0, 0);
        gemm_mma<<<grd, blk, SMEM_BYTES>>>(k, wkT, kp, b_k, 1.0f, DMODEL, PROJD, 0, 0, 0);
        gemm_mma<<<grd, blk, SMEM_BYTES>>>(v, wvT, vp, b_v, 1.0f, DMODEL, PROJD, 0, 0, 0);
    }

    // 1b) Transpose vp per batch: [4096,512] -> [512,4096]
    transpose_kernel<<<dim3(16, 128, BATCH), tblk>>>(vp, vpT, SEQ, PROJD, sP, sP);

    // 2) Scores: S_b = 0.125 * (qp_b @ kp_b^T)
    {
        dim3 grd(SEQ / 128, SEQ / 128, BATCH);
        gemm_mma<<<grd, blk, SMEM_BYTES>>>(qp, kp, S, nullptr, SCALE_QK, PROJD, SEQ, sP, sP, sS);
    }

    // 3) Softmax rows
    softmax_kernel<<<BATCH * SEQ, blk>>>(S);

    // 4) dpa_b = P_b @ vpT_b^T   [4096,512]
    {
        dim3 grd(PROJD / 128, SEQ / 128, BATCH);
        gemm_mma<<<grd, blk, SMEM_BYTES>>>(S, vpT, dpa, nullptr, 1.0f, SEQ, PROJD, sS, sP, sP);
    }

    // 5) out = dpa @ wmT^T + b_mha
    {
        dim3 grd(DMODEL / 128, MFLAT / 128, 1);
        gemm_mma<<<grd, blk, SMEM_BYTES>>>(dpa, wmT, out, b_mha, 1.0f, PROJD, DMODEL, 0, 0, 0);
    }
}

// round 5
// speedup vs baseline: 2.0997x; 1.0816x over previous
#include <cuda_runtime.h>
#include <cuda_fp16.h>
#include <cstdint>

// ---------------------------------------------------------------------------
// Problem constants
// ---------------------------------------------------------------------------
#define BATCH 4
#define SEQ   4096
#define DMODEL 512
#define PROJD  512
#define MFLAT (BATCH * SEQ)
#define SCALE_QK 0.125f

// ---------------------------------------------------------------------------
// Scratch (device globals). hi/lo fp16 planes for every GEMM operand.
// ---------------------------------------------------------------------------
__device__ __align__(16) __half g_qh [MFLAT * DMODEL];
__device__ __align__(16) __half g_ql [MFLAT * DMODEL];
__device__ __align__(16) __half g_kh [MFLAT * DMODEL];
__device__ __align__(16) __half g_kl [MFLAT * DMODEL];
__device__ __align__(16) __half g_vh [MFLAT * DMODEL];
__device__ __align__(16) __half g_vl [MFLAT * DMODEL];
__device__ __align__(16) __half g_wqh[PROJD * DMODEL];
__device__ __align__(16) __half g_wql[PROJD * DMODEL];
__device__ __align__(16) __half g_wkh[PROJD * DMODEL];
__device__ __align__(16) __half g_wkl[PROJD * DMODEL];
__device__ __align__(16) __half g_wvh[PROJD * DMODEL];
__device__ __align__(16) __half g_wvl[PROJD * DMODEL];
__device__ __align__(16) __half g_wmh[DMODEL * PROJD];
__device__ __align__(16) __half g_wml[DMODEL * PROJD];
__device__ __align__(16) __half g_qph[MFLAT * PROJD];
__device__ __align__(16) __half g_qpl[MFLAT * PROJD];
__device__ __align__(16) __half g_kph[MFLAT * PROJD];
__device__ __align__(16) __half g_kpl[MFLAT * PROJD];
__device__ float g_vp[MFLAT * PROJD];
__device__ __align__(16) __half g_vTh[MFLAT * PROJD];
__device__ __align__(16) __half g_vTl[MFLAT * PROJD];
__device__ float g_S[(size_t)BATCH * SEQ * SEQ];
__device__ __align__(16) __half g_Ph[(size_t)BATCH * SEQ * SEQ];
__device__ __align__(16) __half g_Pl[(size_t)BATCH * SEQ * SEQ];
__device__ __align__(16) __half g_dh [MFLAT * PROJD];
__device__ __align__(16) __half g_dl [MFLAT * PROJD];

// ---------------------------------------------------------------------------
// Helpers
// ---------------------------------------------------------------------------
__device__ __forceinline__ uint32_t smem_u32(const void* p) {
    uint32_t a;
    asm("{ .reg .u64 t; cvta.to.shared.u64 t, %1; cvt.u32.u64 %0, t; }"
        : "=r"(a) : "l"(p));
    return a;
}

__device__ __forceinline__ void split2(float x, float y, uint32_t& hi, uint32_t& lo) {
    __half2 h = __floats2half2_rn(x, y);
    float2  f = __half22float2(h);
    __half2 l = __floats2half2_rn(x - f.x, y - f.y);
    hi = *(uint32_t*)&h;
    lo = *(uint32_t*)&l;
}

__device__ __forceinline__ void mma_f16(float* d, const uint32_t* a, const uint32_t* b) {
    asm volatile(
        "mma.sync.aligned.m16n8k16.row.col.f32.f16.f16.f32 "
        "{%0,%1,%2,%3}, {%4,%5,%6,%7}, {%8,%9}, {%0,%1,%2,%3};\n"
        : "+f"(d[0]), "+f"(d[1]), "+f"(d[2]), "+f"(d[3])
        : "r"(a[0]), "r"(a[1]), "r"(a[2]), "r"(a[3]),
          "r"(b[0]), "r"(b[1]));
}

#define LDM4(r, addr) \
    asm volatile("ldmatrix.sync.aligned.m8n8.x4.shared.b16 {%0,%1,%2,%3}, [%4];" \
        : "=r"((r)[0]), "=r"((r)[1]), "=r"((r)[2]), "=r"((r)[3]) : "r"(addr))

#define CP_COMMIT() asm volatile("cp.async.commit_group;" ::: "memory")
#define CP_WAIT(n)  asm volatile("cp.async.wait_group %0;" :: "n"(n) : "memory")

// ---------------------------------------------------------------------------
// gemm16: C[M,N] = scale*(A @ B^T) + bias, A/B pre-split hi/lo fp16 planes.
//   A: [M,K] row-major (both planes).  B: [N,K] row-major.  K mult of 32.
//   CTA tile 128x128, BK=32, 8 warps (4M x 2N), warp tile 32x64.
//   acc += Ah*Bh + Ah*Bl + Al*Bh  (fp32 accum; drops lo*lo ~2^-22).
//   SMEM row = [hi k0..31 (64B) | lo k0..31 (64B) | pad 16B] = 144B pitch.
//   MODE 0: write fp32 C.  MODE 1: write split hi/lo fp16 planes.
// ---------------------------------------------------------------------------
#define STAGES 4
#define ROWB 144
#define TILE_BYTES (128 * ROWB)              // 18432
#define STAGE_BYTES (2 * TILE_BYTES)         // 36864 (A + B)
#define SMEM_TOTAL (STAGES * STAGE_BYTES)    // 147456

__device__ __forceinline__ void cp_issue(uint32_t sbase,
    const __half* __restrict__ Ah, const __half* __restrict__ Al,
    const __half* __restrict__ Bh, const __half* __restrict__ Bl,
    int k0, int K, int tid)
{
    #pragma unroll
    for (int i = 0; i < 8; i++) {
        const int c   = tid + i * 256;      // 0..2047
        const int isB = c >> 10;            // first 1024: A, rest: B
        const int cc  = c & 1023;
        const int row = cc >> 3, seg = cc & 7;
        const __half* hp = isB ? Bh : Ah;
        const __half* lp = isB ? Bl : Al;
        const __half* src = (seg < 4)
            ? hp + (long long)row * K + k0 + seg * 8
            : lp + (long long)row * K + k0 + (seg - 4) * 8;
        const uint32_t dst = sbase + isB * TILE_BYTES + row * ROWB +
                             ((seg < 4) ? seg * 16 : 64 + (seg - 4) * 16);
        asm volatile("cp.async.cg.shared.global [%0], [%1], 16;"
                     :: "r"(dst), "l"(src) : "memory");
    }
}

template <int MODE>
__global__ void __launch_bounds__(256)
gemm16(const __half* __restrict__ Ah, const __half* __restrict__ Al,
       const __half* __restrict__ Bh, const __half* __restrict__ Bl,
       float* __restrict__ Cf, __half* __restrict__ Ch, __half* __restrict__ Cl,
       const float* __restrict__ bias, float scale, int K, int ldC,
       long long sA, long long sB, long long sC)
{
    extern __shared__ char smem[];
    const uint32_t sb = smem_u32(smem);
    const int tid = threadIdx.x, wid = tid >> 5, lane = tid & 31;
    const int g = lane >> 2, tg = lane & 3;
    const int wm = wid & 3, wn = wid >> 2;
    const long long m0 = (long long)blockIdx.y * 128;
    const long long n0 = (long long)blockIdx.x * 128;
    const long long zA = (long long)blockIdx.z * sA;
    const long long zB = (long long)blockIdx.z * sB;
    const long long zC = (long long)blockIdx.z * sC;

    const __half* Ah0 = Ah + zA + m0 * K;
    const __half* Al0 = Al + zA + m0 * K;
    const __half* Bh0 = Bh + zB + n0 * K;
    const __half* Bl0 = Bl + zB + n0 * K;

    // ldmatrix per-lane address offsets
    const int fj = lane >> 3, fr = lane & 7;
    const uint32_t a_off = ((fj & 1) * 8 + fr) * ROWB + (fj >> 1) * 16;
    const uint32_t b_off = ((fj >> 1) * 8 + fr) * ROWB + (fj & 1) * 16;

    float acc[2][8][4];
    #pragma unroll
    for (int i = 0; i < 2; i++)
        #pragma unroll
        for (int j = 0; j < 8; j++)
            #pragma unroll
            for (int l = 0; l < 4; l++) acc[i][j][l] = 0.0f;

    const int nch = K >> 5;

    #pragma unroll
    for (int s = 0; s < STAGES - 1; s++) {
        cp_issue(sb + s * STAGE_BYTES, Ah0, Al0, Bh0, Bl0, s * 32, K, tid);
        CP_COMMIT();
    }

    #pragma unroll 1
    for (int c = 0; c < nch; c++) {
        CP_WAIT(STAGES - 2);
        __syncthreads();
        const int nx = c + STAGES - 1;
        if (nx < nch)
            cp_issue(sb + (nx % STAGES) * STAGE_BYTES, Ah0, Al0, Bh0, Bl0, nx * 32, K, tid);
        CP_COMMIT();

        const uint32_t asb = sb + (c % STAGES) * STAGE_BYTES;
        const uint32_t bsb = asb + TILE_BYTES;

        #pragma unroll
        for (int ks = 0; ks < 2; ks++) {
            uint32_t ah[2][4], alo[2][4], bh[4][4], blo[4][4];
            #pragma unroll
            for (int mt = 0; mt < 2; mt++) {
                const uint32_t base = asb + (wm * 32 + mt * 16) * ROWB + ks * 32 + a_off;
                LDM4(ah[mt], base);
                LDM4(alo[mt], base + 64);
            }
            #pragma unroll
            for (int p = 0; p < 4; p++) {
                const uint32_t base = bsb + (wn * 64 + p * 16) * ROWB + ks * 32 + b_off;
                LDM4(bh[p], base);
                LDM4(blo[p], base + 64);
            }
            #pragma unroll
            for (int nt = 0; nt < 8; nt++) {
                const uint32_t* bph = &bh [nt >> 1][(nt & 1) * 2];
                const uint32_t* bpl = &blo[nt >> 1][(nt & 1) * 2];
                mma_f16(acc[0][nt], ah[0],  bph);
                mma_f16(acc[1][nt], ah[1],  bph);
                mma_f16(acc[0][nt], ah[0],  bpl);
                mma_f16(acc[1][nt], ah[1],  bpl);
                mma_f16(acc[0][nt], alo[0], bph);
                mma_f16(acc[1][nt], alo[1], bph);
            }
        }
    }

    // ---- epilogue ----
    #pragma unroll
    for (int nt = 0; nt < 8; nt++) {
        const long long ccol = n0 + wn * 64 + nt * 8 + tg * 2;
        const float b0 = bias ? bias[ccol]     : 0.0f;
        const float b1 = bias ? bias[ccol + 1] : 0.0f;
        #pragma unroll
        for (int mt = 0; mt < 2; mt++) {
            const long long rA = m0 + wm * 32 + mt * 16 + g;
            const long long rB = rA + 8;
            const float f0 = acc[mt][nt][0] * scale + b0;
            const float f1 = acc[mt][nt][1] * scale + b1;
            const float f2 = acc[mt][nt][2] * scale + b0;
            const float f3 = acc[mt][nt][3] * scale + b1;
            if (MODE == 0) {
                *(float2*)(Cf + zC + rA * ldC + ccol) = make_float2(f0, f1);
                *(float2*)(Cf + zC + rB * ldC + ccol) = make_float2(f2, f3);
            } else {
                uint32_t h, l;
                split2(f0, f1, h, l);
                *(uint32_t*)(Ch + zC + rA * ldC + ccol) = h;
                *(uint32_t*)(Cl + zC + rA * ldC + ccol) = l;
                split2(f2, f3, h, l);
                *(uint32_t*)(Ch + zC + rB * ldC + ccol) = h;
                *(uint32_t*)(Cl + zC + rB * ldC + ccol) = l;
            }
        }
    }
}

// ---------------------------------------------------------------------------
// Elementwise split fp32 -> hi/lo fp16 planes
// ---------------------------------------------------------------------------
__global__ void __launch_bounds__(256)
split_kernel(const float* __restrict__ in, __half* __restrict__ oh,
             __half* __restrict__ ol, int n4)
{
    const int i = blockIdx.x * 256 + threadIdx.x;
    if (i < n4) {
        float4 f = ((const float4*)in)[i];
        uint32_t h0, l0, h1, l1;
        split2(f.x, f.y, h0, l0);
        split2(f.z, f.w, h1, l1);
        ((uint32_t*)oh)[2 * i]     = h0;
        ((uint32_t*)oh)[2 * i + 1] = h1;
        ((uint32_t*)ol)[2 * i]     = l0;
        ((uint32_t*)ol)[2 * i + 1] = l1;
    }
}

// ---------------------------------------------------------------------------
// Transpose + split: fp32 [rows,cols] -> hi/lo fp16 [cols,rows]
// ---------------------------------------------------------------------------
__global__ void __launch_bounds__(256)
transpose_split(const float* __restrict__ in, __half* __restrict__ oh,
                __half* __restrict__ ol, int rows, int cols,
                long long sIn, long long sOut)
{
    __shared__ float t[32][33];
    in += (long long)blockIdx.z * sIn;
    const int tx = threadIdx.x, ty = threadIdx.y;
    const int c0 = blockIdx.x * 32, r0 = blockIdx.y * 32;
    #pragma unroll
    for (int i = ty; i < 32; i += 8)
        t[i][tx] = in[(long long)(r0 + i) * cols + c0 + tx];
    __syncthreads();
    #pragma unroll
    for (int i = ty; i < 32; i += 8) {
        const long long idx = (long long)blockIdx.z * sOut + (long long)(c0 + i) * rows + r0 + tx;
        const float x = t[tx][i];
        const __half h = __float2half_rn(x);
        oh[idx] = h;
        ol[idx] = __float2half_rn(x - __half2float(h));
    }
}

// ---------------------------------------------------------------------------
// Row softmax: read S fp32, write P hi/lo fp16 planes
// ---------------------------------------------------------------------------
__global__ void __launch_bounds__(256)
softmax_kernel(const float* __restrict__ S, __half* __restrict__ Ph,
               __half* __restrict__ Pl)
{
    const int row = blockIdx.x;
    const float4* p4 = (const float4*)(S + (size_t)row * SEQ);
    const int tid = threadIdx.x;

    float4 v[4];
    float m = -1e30f;
    #pragma unroll
    for (int i = 0; i < 4; i++) {
        v[i] = p4[tid + i * 256];
        m = fmaxf(m, fmaxf(fmaxf(v[i].x, v[i].y), fmaxf(v[i].z, v[i].w)));
    }

    __shared__ float red[8];
    #pragma unroll
    for (int o = 16; o > 0; o >>= 1) m = fmaxf(m, __shfl_xor_sync(0xffffffffu, m, o));
    if ((tid & 31) == 0) red[tid >> 5] = m;
    __syncthreads();
    if (tid == 0) {
        float t = red[0];
        #pragma unroll
        for (int w = 1; w < 8; w++) t = fmaxf(t, red[w]);
        red[0] = t;
    }
    __syncthreads();
    m = red[0];
    __syncthreads();

    float s = 0.0f;
    #pragma unroll
    for (int i = 0; i < 4; i++) {
        v[i].x = __expf(v[i].x - m);  s += v[i].x;
        v[i].y = __expf(v[i].y - m);  s += v[i].y;
        v[i].z = __expf(v[i].z - m);  s += v[i].z;
        v[i].w = __expf(v[i].w - m);  s += v[i].w;
    }
    #pragma unroll
    for (int o = 16; o > 0; o >>= 1) s += __shfl_xor_sync(0xffffffffu, s, o);
    if ((tid & 31) == 0) red[tid >> 5] = s;
    __syncthreads();
    if (tid == 0) {
        float t = 0.0f;
        #pragma unroll
        for (int w = 0; w < 8; w++) t += red[w];
        red[0] = t;
    }
    __syncthreads();
    const float inv = 1.0f / red[0];

    uint32_t* ph = (uint32_t*)(Ph + (size_t)row * SEQ);
    uint32_t* pl = (uint32_t*)(Pl + (size_t)row * SEQ);
    #pragma unroll
    for (int i = 0; i < 4; i++) {
        const int e = tid + i * 256;
        uint32_t h0, l0, h1, l1;
        split2(v[i].x * inv, v[i].y * inv, h0, l0);
        split2(v[i].z * inv, v[i].w * inv, h1, l1);
        ph[2 * e]     = h0;
        ph[2 * e + 1] = h1;
        pl[2 * e]     = l0;
        pl[2 * e + 1] = l1;
    }
}

// ---------------------------------------------------------------------------
// Launch
// ---------------------------------------------------------------------------
extern "C" void kernel_launch(void* const* d_in, const int* in_sizes, int n_in,
                              void* d_out, int out_size)
{
    const float* q     = (const float*)d_in[0];
    const float* k     = (const float*)d_in[1];
    const float* v     = (const float*)d_in[2];
    const float* w_q   = (const float*)d_in[3];
    const float* w_k   = (const float*)d_in[4];
    const float* w_v   = (const float*)d_in[5];
    const float* w_mha = (const float*)d_in[6];
    const float* b_q   = (const float*)d_in[7];
    const float* b_k   = (const float*)d_in[8];
    const float* b_v   = (const float*)d_in[9];
    const float* b_mha = (const float*)d_in[10];
    float* out = (float*)d_out;

    __half *qh,*ql,*kh,*kl,*vh,*vl, *wqh,*wql,*wkh,*wkl,*wvh,*wvl,*wmh,*wml;
    __half *qph,*qpl,*kph,*kpl,*vTh,*vTl,*Ph,*Pl,*dh,*dl;
    float *vp, *S;
    cudaGetSymbolAddress((void**)&qh,  g_qh);  cudaGetSymbolAddress((void**)&ql,  g_ql);
    cudaGetSymbolAddress((void**)&kh,  g_kh);  cudaGetSymbolAddress((void**)&kl,  g_kl);
    cudaGetSymbolAddress((void**)&vh,  g_vh);  cudaGetSymbolAddress((void**)&vl,  g_vl);
    cudaGetSymbolAddress((void**)&wqh, g_wqh); cudaGetSymbolAddress((void**)&wql, g_wql);
    cudaGetSymbolAddress((void**)&wkh, g_wkh); cudaGetSymbolAddress((void**)&wkl, g_wkl);
    cudaGetSymbolAddress((void**)&wvh, g_wvh); cudaGetSymbolAddress((void**)&wvl, g_wvl);
    cudaGetSymbolAddress((void**)&wmh, g_wmh); cudaGetSymbolAddress((void**)&wml, g_wml);
    cudaGetSymbolAddress((void**)&qph, g_qph); cudaGetSymbolAddress((void**)&qpl, g_qpl);
    cudaGetSymbolAddress((void**)&kph, g_kph); cudaGetSymbolAddress((void**)&kpl, g_kpl);
    cudaGetSymbolAddress((void**)&vTh, g_vTh); cudaGetSymbolAddress((void**)&vTl, g_vTl);
    cudaGetSymbolAddress((void**)&Ph,  g_Ph);  cudaGetSymbolAddress((void**)&Pl,  g_Pl);
    cudaGetSymbolAddress((void**)&dh,  g_dh);  cudaGetSymbolAddress((void**)&dl,  g_dl);
    cudaGetSymbolAddress((void**)&vp,  g_vp);  cudaGetSymbolAddress((void**)&S,   g_S);

    const long long sP = (long long)SEQ * PROJD;
    const long long sS = (long long)SEQ * SEQ;

    cudaFuncSetAttribute(gemm16<0>, cudaFuncAttributeMaxDynamicSharedMemorySize, SMEM_TOTAL);
    cudaFuncSetAttribute(gemm16<1>, cudaFuncAttributeMaxDynamicSharedMemorySize, SMEM_TOTAL);

    dim3 tblk(32, 8);

    // 0) Split inputs; transpose+split weights
    const int n4 = MFLAT * DMODEL / 4;
    split_kernel<<<n4 / 256, 256>>>(q, qh, ql, n4);
    split_kernel<<<n4 / 256, 256>>>(k, kh, kl, n4);
    split_kernel<<<n4 / 256, 256>>>(v, vh, vl, n4);
    transpose_split<<<dim3(16, 16, 1), tblk>>>(w_q,   wqh, wql, DMODEL, PROJD, 0, 0);
    transpose_split<<<dim3(16, 16, 1), tblk>>>(w_k,   wkh, wkl, DMODEL, PROJD, 0, 0);
    transpose_split<<<dim3(16, 16, 1), tblk>>>(w_v,   wvh, wvl, DMODEL, PROJD, 0, 0);
    transpose_split<<<dim3(16, 16, 1), tblk>>>(w_mha, wmh, wml, PROJD, DMODEL, 0, 0);

    // 1) Projections
    {
        dim3 grd(PROJD / 128, MFLAT / 128, 1);
        gemm16<1><<<grd, 256, SMEM_TOTAL>>>(qh, ql, wqh, wql, nullptr, qph, qpl,
                                            b_q, 1.0f, DMODEL, PROJD, 0, 0, 0);
        gemm16<1><<<grd, 256, SMEM_TOTAL>>>(kh, kl, wkh, wkl, nullptr, kph, kpl,
                                            b_k, 1.0f, DMODEL, PROJD, 0, 0, 0);
        gemm16<0><<<grd, 256, SMEM_TOTAL>>>(vh, vl, wvh, wvl, vp, nullptr, nullptr,
                                            b_v, 1.0f, DMODEL, PROJD, 0, 0, 0);
    }

    // 1b) vp -> vpT split planes
    transpose_split<<<dim3(16, 128, BATCH), tblk>>>(vp, vTh, vTl, SEQ, PROJD, sP, sP);

    // 2) S = 0.125 * qp @ kp^T  (fp32)
    gemm16<0><<<dim3(SEQ / 128, SEQ / 128, BATCH), 256, SMEM_TOTAL>>>(
        qph, qpl, kph, kpl, S, nullptr, nullptr, nullptr, SCALE_QK,
        PROJD, SEQ, sP, sP, sS);

    // 3) softmax -> P split planes
    softmax_kernel<<<BATCH * SEQ, 256>>>(S, Ph, Pl);

    // 4) dpa = P @ vpT^T -> split planes
    gemm16<1><<<dim3(PROJD / 128, SEQ / 128, BATCH), 256, SMEM_TOTAL>>>(
        Ph, Pl, vTh, vTl, nullptr, dh, dl, nullptr, 1.0f,
        SEQ, PROJD, sS, sP, sP);

    // 5) out = dpa @ wm^T + b_mha  (fp32)
    gemm16<0><<<dim3(DMODEL / 128, MFLAT / 128, 1), 256, SMEM_TOTAL>>>(
        dh, dl, wmh, wml, out, nullptr, nullptr, b_mha, 1.0f,
        PROJD, DMODEL, 0, 0, 0);
}

// round 6
// speedup vs baseline: 2.6725x; 1.2728x over previous
#include <cuda_runtime.h>
#include <cuda_fp16.h>
#include <cstdint>

// ---------------------------------------------------------------------------
// Problem constants
// ---------------------------------------------------------------------------
#define BATCH 4
#define SEQ   4096
#define DMODEL 512
#define PROJD  512
#define MFLAT (BATCH * SEQ)
#define SCALE_QK 0.125f

// ---------------------------------------------------------------------------
// Scratch (device globals). hi/lo fp16 planes for every GEMM operand.
// ---------------------------------------------------------------------------
__device__ __align__(16) __half g_qh [MFLAT * DMODEL];
__device__ __align__(16) __half g_ql [MFLAT * DMODEL];
__device__ __align__(16) __half g_kh [MFLAT * DMODEL];
__device__ __align__(16) __half g_kl [MFLAT * DMODEL];
__device__ __align__(16) __half g_vh [MFLAT * DMODEL];
__device__ __align__(16) __half g_vl [MFLAT * DMODEL];
__device__ __align__(16) __half g_wqh[PROJD * DMODEL];
__device__ __align__(16) __half g_wql[PROJD * DMODEL];
__device__ __align__(16) __half g_wkh[PROJD * DMODEL];
__device__ __align__(16) __half g_wkl[PROJD * DMODEL];
__device__ __align__(16) __half g_wvh[PROJD * DMODEL];
__device__ __align__(16) __half g_wvl[PROJD * DMODEL];
__device__ __align__(16) __half g_wmh[DMODEL * PROJD];
__device__ __align__(16) __half g_wml[DMODEL * PROJD];
__device__ __align__(16) __half g_qph[MFLAT * PROJD];
__device__ __align__(16) __half g_qpl[MFLAT * PROJD];
__device__ __align__(16) __half g_kph[MFLAT * PROJD];
__device__ __align__(16) __half g_kpl[MFLAT * PROJD];
__device__ float g_vp[MFLAT * PROJD];
__device__ __align__(16) __half g_vTh[MFLAT * PROJD];
__device__ __align__(16) __half g_vTl[MFLAT * PROJD];
__device__ float g_S[(size_t)BATCH * SEQ * SEQ];
__device__ __align__(16) __half g_Ph[(size_t)BATCH * SEQ * SEQ];
__device__ __align__(16) __half g_Pl[(size_t)BATCH * SEQ * SEQ];
__device__ __align__(16) __half g_dh [MFLAT * PROJD];
__device__ __align__(16) __half g_dl [MFLAT * PROJD];

// ---------------------------------------------------------------------------
// Helpers
// ---------------------------------------------------------------------------
__device__ __forceinline__ uint32_t smem_u32(const void* p) {
    uint32_t a;
    asm("{ .reg .u64 t; cvta.to.shared.u64 t, %1; cvt.u32.u64 %0, t; }"
        : "=r"(a) : "l"(p));
    return a;
}

__device__ __forceinline__ void split2(float x, float y, uint32_t& hi, uint32_t& lo) {
    __half2 h = __floats2half2_rn(x, y);
    float2  f = __half22float2(h);
    __half2 l = __floats2half2_rn(x - f.x, y - f.y);
    hi = *(uint32_t*)&h;
    lo = *(uint32_t*)&l;
}

__device__ __forceinline__ void mma_f16(float* d, const uint32_t* a, const uint32_t* b) {
    asm volatile(
        "mma.sync.aligned.m16n8k16.row.col.f32.f16.f16.f32 "
        "{%0,%1,%2,%3}, {%4,%5,%6,%7}, {%8,%9}, {%0,%1,%2,%3};\n"
        : "+f"(d[0]), "+f"(d[1]), "+f"(d[2]), "+f"(d[3])
        : "r"(a[0]), "r"(a[1]), "r"(a[2]), "r"(a[3]),
          "r"(b[0]), "r"(b[1]));
}

#define LDM4(r, addr) \
    asm volatile("ldmatrix.sync.aligned.m8n8.x4.shared.b16 {%0,%1,%2,%3}, [%4];" \
        : "=r"((r)[0]), "=r"((r)[1]), "=r"((r)[2]), "=r"((r)[3]) : "r"(addr))

#define CP_COMMIT() asm volatile("cp.async.commit_group;" ::: "memory")
#define CP_WAIT(n)  asm volatile("cp.async.wait_group %0;" :: "n"(n) : "memory")

// ---------------------------------------------------------------------------
// gemm16: C[M,N] = scale*(A @ B^T) + bias, A/B pre-split hi/lo fp16 planes.
//   CTA tile 128x128, BK=32, 8 warps (4M x 2N), warp tile 32x64.
//   acc += Ah*Bh + Ah*Bl + Al*Bh, with term-outermost MMA ordering so
//   dependent MMAs on one accumulator are 16 instructions apart.
//   3-stage cp.async ring (110.6 KB) -> 2 CTAs/SM.
// ---------------------------------------------------------------------------
#define STAGES 3
#define ROWB 144
#define TILE_BYTES (128 * ROWB)              // 18432
#define STAGE_BYTES (2 * TILE_BYTES)         // 36864 (A + B)
#define SMEM_TOTAL (STAGES * STAGE_BYTES)    // 110592

__device__ __forceinline__ void cp_issue(uint32_t sbase,
    const __half* __restrict__ Ah, const __half* __restrict__ Al,
    const __half* __restrict__ Bh, const __half* __restrict__ Bl,
    int k0, int K, int tid)
{
    #pragma unroll
    for (int i = 0; i < 8; i++) {
        const int c   = tid + i * 256;      // 0..2047
        const int isB = c >> 10;
        const int cc  = c & 1023;
        const int row = cc >> 3, seg = cc & 7;
        const __half* hp = isB ? Bh : Ah;
        const __half* lp = isB ? Bl : Al;
        const __half* src = (seg < 4)
            ? hp + (long long)row * K + k0 + seg * 8
            : lp + (long long)row * K + k0 + (seg - 4) * 8;
        const uint32_t dst = sbase + isB * TILE_BYTES + row * ROWB +
                             ((seg < 4) ? seg * 16 : 64 + (seg - 4) * 16);
        asm volatile("cp.async.cg.shared.global [%0], [%1], 16;"
                     :: "r"(dst), "l"(src) : "memory");
    }
}

template <int MODE>
__global__ void __launch_bounds__(256, 2)
gemm16(const __half* __restrict__ Ah, const __half* __restrict__ Al,
       const __half* __restrict__ Bh, const __half* __restrict__ Bl,
       float* __restrict__ Cf, __half* __restrict__ Ch, __half* __restrict__ Cl,
       const float* __restrict__ bias, float scale, int K, int ldC,
       long long sA, long long sB, long long sC)
{
    extern __shared__ char smem[];
    const uint32_t sb = smem_u32(smem);
    const int tid = threadIdx.x, wid = tid >> 5, lane = tid & 31;
    const int g = lane >> 2, tg = lane & 3;
    const int wm = wid & 3, wn = wid >> 2;
    const long long m0 = (long long)blockIdx.y * 128;
    const long long n0 = (long long)blockIdx.x * 128;
    const long long zA = (long long)blockIdx.z * sA;
    const long long zB = (long long)blockIdx.z * sB;
    const long long zC = (long long)blockIdx.z * sC;

    const __half* Ah0 = Ah + zA + m0 * K;
    const __half* Al0 = Al + zA + m0 * K;
    const __half* Bh0 = Bh + zB + n0 * K;
    const __half* Bl0 = Bl + zB + n0 * K;

    // ldmatrix per-lane address offsets
    const int fj = lane >> 3, fr = lane & 7;
    const uint32_t a_off = ((fj & 1) * 8 + fr) * ROWB + (fj >> 1) * 16;
    const uint32_t b_off = ((fj >> 1) * 8 + fr) * ROWB + (fj & 1) * 16;

    float acc[2][8][4];
    #pragma unroll
    for (int i = 0; i < 2; i++)
        #pragma unroll
        for (int j = 0; j < 8; j++)
            #pragma unroll
            for (int l = 0; l < 4; l++) acc[i][j][l] = 0.0f;

    const int nch = K >> 5;

    #pragma unroll
    for (int s = 0; s < STAGES - 1; s++) {
        cp_issue(sb + s * STAGE_BYTES, Ah0, Al0, Bh0, Bl0, s * 32, K, tid);
        CP_COMMIT();
    }

    #pragma unroll 1
    for (int c = 0; c < nch; c++) {
        CP_WAIT(STAGES - 2);
        __syncthreads();
        const int nx = c + STAGES - 1;
        if (nx < nch)
            cp_issue(sb + (nx % STAGES) * STAGE_BYTES, Ah0, Al0, Bh0, Bl0, nx * 32, K, tid);
        CP_COMMIT();

        const uint32_t asb = sb + (c % STAGES) * STAGE_BYTES;
        const uint32_t bsb = asb + TILE_BYTES;

        #pragma unroll
        for (int ks = 0; ks < 2; ks++) {
            uint32_t ah[2][4], alo[2][4], bh[4][4], blo[4][4];
            #pragma unroll
            for (int mt = 0; mt < 2; mt++) {
                const uint32_t base = asb + (wm * 32 + mt * 16) * ROWB + ks * 32 + a_off;
                LDM4(ah[mt], base);
                LDM4(alo[mt], base + 64);
            }
            #pragma unroll
            for (int p = 0; p < 4; p++) {
                const uint32_t base = bsb + (wn * 64 + p * 16) * ROWB + ks * 32 + b_off;
                LDM4(bh[p], base);
                LDM4(blo[p], base + 64);
            }
            // term-outermost: dependent MMAs on one acc are 16 apart
            #pragma unroll
            for (int nt = 0; nt < 8; nt++) {
                const uint32_t* bph = &bh[nt >> 1][(nt & 1) * 2];
                mma_f16(acc[0][nt], ah[0], bph);
                mma_f16(acc[1][nt], ah[1], bph);
            }
            #pragma unroll
            for (int nt = 0; nt < 8; nt++) {
                const uint32_t* bpl = &blo[nt >> 1][(nt & 1) * 2];
                mma_f16(acc[0][nt], ah[0], bpl);
                mma_f16(acc[1][nt], ah[1], bpl);
            }
            #pragma unroll
            for (int nt = 0; nt < 8; nt++) {
                const uint32_t* bph = &bh[nt >> 1][(nt & 1) * 2];
                mma_f16(acc[0][nt], alo[0], bph);
                mma_f16(acc[1][nt], alo[1], bph);
            }
        }
    }

    // ---- epilogue ----
    #pragma unroll
    for (int nt = 0; nt < 8; nt++) {
        const long long ccol = n0 + wn * 64 + nt * 8 + tg * 2;
        const float b0 = bias ? bias[ccol]     : 0.0f;
        const float b1 = bias ? bias[ccol + 1] : 0.0f;
        #pragma unroll
        for (int mt = 0; mt < 2; mt++) {
            const long long rA = m0 + wm * 32 + mt * 16 + g;
            const long long rB = rA + 8;
            const float f0 = acc[mt][nt][0] * scale + b0;
            const float f1 = acc[mt][nt][1] * scale + b1;
            const float f2 = acc[mt][nt][2] * scale + b0;
            const float f3 = acc[mt][nt][3] * scale + b1;
            if (MODE == 0) {
                *(float2*)(Cf + zC + rA * ldC + ccol) = make_float2(f0, f1);
                *(float2*)(Cf + zC + rB * ldC + ccol) = make_float2(f2, f3);
            } else {
                uint32_t h, l;
                split2(f0, f1, h, l);
                *(uint32_t*)(Ch + zC + rA * ldC + ccol) = h;
                *(uint32_t*)(Cl + zC + rA * ldC + ccol) = l;
                split2(f2, f3, h, l);
                *(uint32_t*)(Ch + zC + rB * ldC + ccol) = h;
                *(uint32_t*)(Cl + zC + rB * ldC + ccol) = l;
            }
        }
    }
}

// ---------------------------------------------------------------------------
// Elementwise split fp32 -> hi/lo fp16 planes
// ---------------------------------------------------------------------------
__global__ void __launch_bounds__(256)
split_kernel(const float* __restrict__ in, __half* __restrict__ oh,
             __half* __restrict__ ol, int n4)
{
    const int i = blockIdx.x * 256 + threadIdx.x;
    if (i < n4) {
        float4 f = ((const float4*)in)[i];
        uint32_t h0, l0, h1, l1;
        split2(f.x, f.y, h0, l0);
        split2(f.z, f.w, h1, l1);
        ((uint32_t*)oh)[2 * i]     = h0;
        ((uint32_t*)oh)[2 * i + 1] = h1;
        ((uint32_t*)ol)[2 * i]     = l0;
        ((uint32_t*)ol)[2 * i + 1] = l1;
    }
}

// ---------------------------------------------------------------------------
// Transpose + split: fp32 [rows,cols] -> hi/lo fp16 [cols,rows]
// ---------------------------------------------------------------------------
__global__ void __launch_bounds__(256)
transpose_split(const float* __restrict__ in, __half* __restrict__ oh,
                __half* __restrict__ ol, int rows, int cols,
                long long sIn, long long sOut)
{
    __shared__ float t[32][33];
    in += (long long)blockIdx.z * sIn;
    const int tx = threadIdx.x, ty = threadIdx.y;
    const int c0 = blockIdx.x * 32, r0 = blockIdx.y * 32;
    #pragma unroll
    for (int i = ty; i < 32; i += 8)
        t[i][tx] = in[(long long)(r0 + i) * cols + c0 + tx];
    __syncthreads();
    #pragma unroll
    for (int i = ty; i < 32; i += 8) {
        const long long idx = (long long)blockIdx.z * sOut + (long long)(c0 + i) * rows + r0 + tx;
        const float x = t[tx][i];
        const __half h = __float2half_rn(x);
        oh[idx] = h;
        ol[idx] = __float2half_rn(x - __half2float(h));
    }
}

// ---------------------------------------------------------------------------
// Row softmax: read S fp32, write P hi/lo fp16 planes
// ---------------------------------------------------------------------------
__global__ void __launch_bounds__(256)
softmax_kernel(const float* __restrict__ S, __half* __restrict__ Ph,
               __half* __restrict__ Pl)
{
    const int row = blockIdx.x;
    const float4* p4 = (const float4*)(S + (size_t)row * SEQ);
    const int tid = threadIdx.x;

    float4 v[4];
    float m = -1e30f;
    #pragma unroll
    for (int i = 0; i < 4; i++) {
        v[i] = p4[tid + i * 256];
        m = fmaxf(m, fmaxf(fmaxf(v[i].x, v[i].y), fmaxf(v[i].z, v[i].w)));
    }

    __shared__ float red[8];
    #pragma unroll
    for (int o = 16; o > 0; o >>= 1) m = fmaxf(m, __shfl_xor_sync(0xffffffffu, m, o));
    if ((tid & 31) == 0) red[tid >> 5] = m;
    __syncthreads();
    if (tid == 0) {
        float t = red[0];
        #pragma unroll
        for (int w = 1; w < 8; w++) t = fmaxf(t, red[w]);
        red[0] = t;
    }
    __syncthreads();
    m = red[0];
    __syncthreads();

    float s = 0.0f;
    #pragma unroll
    for (int i = 0; i < 4; i++) {
        v[i].x = __expf(v[i].x - m);  s += v[i].x;
        v[i].y = __expf(v[i].y - m);  s += v[i].y;
        v[i].z = __expf(v[i].z - m);  s += v[i].z;
        v[i].w = __expf(v[i].w - m);  s += v[i].w;
    }
    #pragma unroll
    for (int o = 16; o > 0; o >>= 1) s += __shfl_xor_sync(0xffffffffu, s, o);
    if ((tid & 31) == 0) red[tid >> 5] = s;
    __syncthreads();
    if (tid == 0) {
        float t = 0.0f;
        #pragma unroll
        for (int w = 0; w < 8; w++) t += red[w];
        red[0] = t;
    }
    __syncthreads();
    const float inv = 1.0f / red[0];

    uint32_t* ph = (uint32_t*)(Ph + (size_t)row * SEQ);
    uint32_t* pl = (uint32_t*)(Pl + (size_t)row * SEQ);
    #pragma unroll
    for (int i = 0; i < 4; i++) {
        const int e = tid + i * 256;
        uint32_t h0, l0, h1, l1;
        split2(v[i].x * inv, v[i].y * inv, h0, l0);
        split2(v[i].z * inv, v[i].w * inv, h1, l1);
        ph[2 * e]     = h0;
        ph[2 * e + 1] = h1;
        pl[2 * e]     = l0;
        pl[2 * e + 1] = l1;
    }
}

// ---------------------------------------------------------------------------
// Launch
// ---------------------------------------------------------------------------
extern "C" void kernel_launch(void* const* d_in, const int* in_sizes, int n_in,
                              void* d_out, int out_size)
{
    const float* q     = (const float*)d_in[0];
    const float* k     = (const float*)d_in[1];
    const float* v     = (const float*)d_in[2];
    const float* w_q   = (const float*)d_in[3];
    const float* w_k   = (const float*)d_in[4];
    const float* w_v   = (const float*)d_in[5];
    const float* w_mha = (const float*)d_in[6];
    const float* b_q   = (const float*)d_in[7];
    const float* b_k   = (const float*)d_in[8];
    const float* b_v   = (const float*)d_in[9];
    const float* b_mha = (const float*)d_in[10];
    float* out = (float*)d_out;

    __half *qh,*ql,*kh,*kl,*vh,*vl, *wqh,*wql,*wkh,*wkl,*wvh,*wvl,*wmh,*wml;
    __half *qph,*qpl,*kph,*kpl,*vTh,*vTl,*Ph,*Pl,*dh,*dl;
    float *vp, *S;
    cudaGetSymbolAddress((void**)&qh,  g_qh);  cudaGetSymbolAddress((void**)&ql,  g_ql);
    cudaGetSymbolAddress((void**)&kh,  g_kh);  cudaGetSymbolAddress((void**)&kl,  g_kl);
    cudaGetSymbolAddress((void**)&vh,  g_vh);  cudaGetSymbolAddress((void**)&vl,  g_vl);
    cudaGetSymbolAddress((void**)&wqh, g_wqh); cudaGetSymbolAddress((void**)&wql, g_wql);
    cudaGetSymbolAddress((void**)&wkh, g_wkh); cudaGetSymbolAddress((void**)&wkl, g_wkl);
    cudaGetSymbolAddress((void**)&wvh, g_wvh); cudaGetSymbolAddress((void**)&wvl, g_wvl);
    cudaGetSymbolAddress((void**)&wmh, g_wmh); cudaGetSymbolAddress((void**)&wml, g_wml);
    cudaGetSymbolAddress((void**)&qph, g_qph); cudaGetSymbolAddress((void**)&qpl, g_qpl);
    cudaGetSymbolAddress((void**)&kph, g_kph); cudaGetSymbolAddress((void**)&kpl, g_kpl);
    cudaGetSymbolAddress((void**)&vTh, g_vTh); cudaGetSymbolAddress((void**)&vTl, g_vTl);
    cudaGetSymbolAddress((void**)&Ph,  g_Ph);  cudaGetSymbolAddress((void**)&Pl,  g_Pl);
    cudaGetSymbolAddress((void**)&dh,  g_dh);  cudaGetSymbolAddress((void**)&dl,  g_dl);
    cudaGetSymbolAddress((void**)&vp,  g_vp);  cudaGetSymbolAddress((void**)&S,   g_S);

    const long long sP = (long long)SEQ * PROJD;
    const long long sS = (long long)SEQ * SEQ;

    cudaFuncSetAttribute(gemm16<0>, cudaFuncAttributeMaxDynamicSharedMemorySize, SMEM_TOTAL);
    cudaFuncSetAttribute(gemm16<1>, cudaFuncAttributeMaxDynamicSharedMemorySize, SMEM_TOTAL);

    dim3 tblk(32, 8);

    // 0) Split inputs; transpose+split weights
    const int n4 = MFLAT * DMODEL / 4;
    split_kernel<<<n4 / 256, 256>>>(q, qh, ql, n4);
    split_kernel<<<n4 / 256, 256>>>(k, kh, kl, n4);
    split_kernel<<<n4 / 256, 256>>>(v, vh, vl, n4);
    transpose_split<<<dim3(16, 16, 1), tblk>>>(w_q,   wqh, wql, DMODEL, PROJD, 0, 0);
    transpose_split<<<dim3(16, 16, 1), tblk>>>(w_k,   wkh, wkl, DMODEL, PROJD, 0, 0);
    transpose_split<<<dim3(16, 16, 1), tblk>>>(w_v,   wvh, wvl, DMODEL, PROJD, 0, 0);
    transpose_split<<<dim3(16, 16, 1), tblk>>>(w_mha, wmh, wml, PROJD, DMODEL, 0, 0);

    // 1) Projections
    {
        dim3 grd(PROJD / 128, MFLAT / 128, 1);
        gemm16<1><<<grd, 256, SMEM_TOTAL>>>(qh, ql, wqh, wql, nullptr, qph, qpl,
                                            b_q, 1.0f, DMODEL, PROJD, 0, 0, 0);
        gemm16<1><<<grd, 256, SMEM_TOTAL>>>(kh, kl, wkh, wkl, nullptr, kph, kpl,
                                            b_k, 1.0f, DMODEL, PROJD, 0, 0, 0);
        gemm16<0><<<grd, 256, SMEM_TOTAL>>>(vh, vl, wvh, wvl, vp, nullptr, nullptr,
                                            b_v, 1.0f, DMODEL, PROJD, 0, 0, 0);
    }

    // 1b) vp -> vpT split planes
    transpose_split<<<dim3(16, 128, BATCH), tblk>>>(vp, vTh, vTl, SEQ, PROJD, sP, sP);

    // 2) S = 0.125 * qp @ kp^T  (fp32)
    gemm16<0><<<dim3(SEQ / 128, SEQ / 128, BATCH), 256, SMEM_TOTAL>>>(
        qph, qpl, kph, kpl, S, nullptr, nullptr, nullptr, SCALE_QK,
        PROJD, SEQ, sP, sP, sS);

    // 3) softmax -> P split planes
    softmax_kernel<<<BATCH * SEQ, 256>>>(S, Ph, Pl);

    // 4) dpa = P @ vpT^T -> split planes
    gemm16<1><<<dim3(PROJD / 128, SEQ / 128, BATCH), 256, SMEM_TOTAL>>>(
        Ph, Pl, vTh, vTl, nullptr, dh, dl, nullptr, 1.0f,
        SEQ, PROJD, sS, sP, sP);

    // 5) out = dpa @ wm^T + b_mha  (fp32)
    gemm16<0><<<dim3(DMODEL / 128, MFLAT / 128, 1), 256, SMEM_TOTAL>>>(
        dh, dl, wmh, wml, out, nullptr, nullptr, b_mha, 1.0f,
        PROJD, DMODEL, 0, 0, 0);
}

// round 7
// speedup vs baseline: 3.0480x; 1.1405x over previous
#include <cuda_runtime.h>
#include <cuda_fp16.h>
#include <cstdint>

// ---------------------------------------------------------------------------
// Problem constants
// ---------------------------------------------------------------------------
#define BATCH 4
#define SEQ   4096
#define DMODEL 512
#define PROJD  512
#define MFLAT (BATCH * SEQ)
#define SCALE_QK 0.125f

// ---------------------------------------------------------------------------
// Scratch (device globals). hi/lo fp16 planes per GEMM operand.
// ---------------------------------------------------------------------------
__device__ __align__(16) __half g_qh [MFLAT * DMODEL];
__device__ __align__(16) __half g_ql [MFLAT * DMODEL];
__device__ __align__(16) __half g_kh [MFLAT * DMODEL];
__device__ __align__(16) __half g_kl [MFLAT * DMODEL];
__device__ __align__(16) __half g_vh [MFLAT * DMODEL];
__device__ __align__(16) __half g_vl [MFLAT * DMODEL];
__device__ __align__(16) __half g_wqh[PROJD * DMODEL];
__device__ __align__(16) __half g_wql[PROJD * DMODEL];
__device__ __align__(16) __half g_wkh[PROJD * DMODEL];
__device__ __align__(16) __half g_wkl[PROJD * DMODEL];
__device__ __align__(16) __half g_wvh[PROJD * DMODEL];
__device__ __align__(16) __half g_wvl[PROJD * DMODEL];
__device__ __align__(16) __half g_wmh[DMODEL * PROJD];
__device__ __align__(16) __half g_wml[DMODEL * PROJD];
__device__ __align__(16) __half g_qph[MFLAT * PROJD];
__device__ __align__(16) __half g_qpl[MFLAT * PROJD];
__device__ __align__(16) __half g_kph[MFLAT * PROJD];
__device__ __align__(16) __half g_kpl[MFLAT * PROJD];
__device__ float g_vp[MFLAT * PROJD];
__device__ __align__(16) __half g_vTh[MFLAT * PROJD];
__device__ __align__(16) __half g_vTl[MFLAT * PROJD];
__device__ float g_S[(size_t)BATCH * SEQ * SEQ];
__device__ __align__(16) __half g_Ph[(size_t)BATCH * SEQ * SEQ];   // hi plane only
__device__ __align__(16) __half g_dh [MFLAT * PROJD];              // hi plane only

// ---------------------------------------------------------------------------
// Helpers
// ---------------------------------------------------------------------------
__device__ __forceinline__ uint32_t smem_u32(const void* p) {
    uint32_t a;
    asm("{ .reg .u64 t; cvta.to.shared.u64 t, %1; cvt.u32.u64 %0, t; }"
        : "=r"(a) : "l"(p));
    return a;
}

__device__ __forceinline__ void split2(float x, float y, uint32_t& hi, uint32_t& lo) {
    __half2 h = __floats2half2_rn(x, y);
    float2  f = __half22float2(h);
    __half2 l = __floats2half2_rn(x - f.x, y - f.y);
    hi = *(uint32_t*)&h;
    lo = *(uint32_t*)&l;
}

__device__ __forceinline__ void mma_f16(float* d, const uint32_t* a, const uint32_t* b) {
    asm volatile(
        "mma.sync.aligned.m16n8k16.row.col.f32.f16.f16.f32 "
        "{%0,%1,%2,%3}, {%4,%5,%6,%7}, {%8,%9}, {%0,%1,%2,%3};\n"
        : "+f"(d[0]), "+f"(d[1]), "+f"(d[2]), "+f"(d[3])
        : "r"(a[0]), "r"(a[1]), "r"(a[2]), "r"(a[3]),
          "r"(b[0]), "r"(b[1]));
}

#define LDM4(r, addr) \
    asm volatile("ldmatrix.sync.aligned.m8n8.x4.shared.b16 {%0,%1,%2,%3}, [%4];" \
        : "=r"((r)[0]), "=r"((r)[1]), "=r"((r)[2]), "=r"((r)[3]) : "r"(addr))

#define CP_COMMIT() asm volatile("cp.async.commit_group;" ::: "memory")
#define CP_WAIT(n)  asm volatile("cp.async.wait_group %0;" :: "n"(n) : "memory")

// ---------------------------------------------------------------------------
// gemm16<MODE, TERMS>: C[M,N] = scale*(A @ B^T) + bias.
//   TERMS=3: acc += Ah*Bh + Ah*Bl + Al*Bh   (full compensation)
//   TERMS=2: acc += Ah*Bh + Ah*Bl           (A hi-plane only; Al never loaded)
//   MODE 0: fp32 C.  MODE 1: split hi+lo planes.  MODE 2: hi plane only.
//   CTA tile 128x128, BK=32, 8 warps (4M x 2N), 3-stage cp.async, 2 CTA/SM.
// ---------------------------------------------------------------------------
#define STAGES 3
#define ROWB 144
#define TILE_BYTES (128 * ROWB)
#define STAGE_BYTES (2 * TILE_BYTES)
#define SMEM_TOTAL (STAGES * STAGE_BYTES)    // 110592

template <int TERMS>
__device__ __forceinline__ void cp_issue(uint32_t sbase,
    const __half* __restrict__ Ah, const __half* __restrict__ Al,
    const __half* __restrict__ Bh, const __half* __restrict__ Bl,
    int k0, int K, int tid)
{
    #pragma unroll
    for (int i = 0; i < 8; i++) {
        const int c   = tid + i * 256;      // 0..2047
        const int isB = c >> 10;
        const int cc  = c & 1023;
        const int row = cc >> 3, seg = cc & 7;
        if (TERMS == 2 && !isB && seg >= 4) continue;   // skip A-lo
        const __half* hp = isB ? Bh : Ah;
        const __half* lp = isB ? Bl : Al;
        const __half* src = (seg < 4)
            ? hp + (long long)row * K + k0 + seg * 8
            : lp + (long long)row * K + k0 + (seg - 4) * 8;
        const uint32_t dst = sbase + isB * TILE_BYTES + row * ROWB +
                             ((seg < 4) ? seg * 16 : 64 + (seg - 4) * 16);
        asm volatile("cp.async.cg.shared.global [%0], [%1], 16;"
                     :: "r"(dst), "l"(src) : "memory");
    }
}

template <int MODE, int TERMS>
__global__ void __launch_bounds__(256, 2)
gemm16(const __half* __restrict__ Ah, const __half* __restrict__ Al,
       const __half* __restrict__ Bh, const __half* __restrict__ Bl,
       float* __restrict__ Cf, __half* __restrict__ Ch, __half* __restrict__ Cl,
       const float* __restrict__ bias, float scale, int K, int ldC,
       long long sA, long long sB, long long sC)
{
    extern __shared__ char smem[];
    const uint32_t sb = smem_u32(smem);
    const int tid = threadIdx.x, wid = tid >> 5, lane = tid & 31;
    const int g = lane >> 2, tg = lane & 3;
    const int wm = wid & 3, wn = wid >> 2;
    const long long m0 = (long long)blockIdx.y * 128;
    const long long n0 = (long long)blockIdx.x * 128;
    const long long zA = (long long)blockIdx.z * sA;
    const long long zB = (long long)blockIdx.z * sB;
    const long long zC = (long long)blockIdx.z * sC;

    const __half* Ah0 = Ah + zA + m0 * K;
    const __half* Al0 = (TERMS == 3) ? Al + zA + m0 * K : Ah0;
    const __half* Bh0 = Bh + zB + n0 * K;
    const __half* Bl0 = Bl + zB + n0 * K;

    const int fj = lane >> 3, fr = lane & 7;
    const uint32_t a_off = ((fj & 1) * 8 + fr) * ROWB + (fj >> 1) * 16;
    const uint32_t b_off = ((fj >> 1) * 8 + fr) * ROWB + (fj & 1) * 16;

    float acc[2][8][4];
    #pragma unroll
    for (int i = 0; i < 2; i++)
        #pragma unroll
        for (int j = 0; j < 8; j++)
            #pragma unroll
            for (int l = 0; l < 4; l++) acc[i][j][l] = 0.0f;

    const int nch = K >> 5;

    #pragma unroll
    for (int s = 0; s < STAGES - 1; s++) {
        cp_issue<TERMS>(sb + s * STAGE_BYTES, Ah0, Al0, Bh0, Bl0, s * 32, K, tid);
        CP_COMMIT();
    }

    #pragma unroll 1
    for (int c = 0; c < nch; c++) {
        CP_WAIT(STAGES - 2);
        __syncthreads();
        const int nx = c + STAGES - 1;
        if (nx < nch)
            cp_issue<TERMS>(sb + (nx % STAGES) * STAGE_BYTES, Ah0, Al0, Bh0, Bl0, nx * 32, K, tid);
        CP_COMMIT();

        const uint32_t asb = sb + (c % STAGES) * STAGE_BYTES;
        const uint32_t bsb = asb + TILE_BYTES;

        #pragma unroll
        for (int ks = 0; ks < 2; ks++) {
            uint32_t ah[2][4], alo[2][4], bh[4][4], blo[4][4];
            #pragma unroll
            for (int mt = 0; mt < 2; mt++) {
                const uint32_t base = asb + (wm * 32 + mt * 16) * ROWB + ks * 32 + a_off;
                LDM4(ah[mt], base);
                if (TERMS == 3) LDM4(alo[mt], base + 64);
            }
            #pragma unroll
            for (int p = 0; p < 4; p++) {
                const uint32_t base = bsb + (wn * 64 + p * 16) * ROWB + ks * 32 + b_off;
                LDM4(bh[p], base);
                LDM4(blo[p], base + 64);
            }
            #pragma unroll
            for (int nt = 0; nt < 8; nt++) {
                const uint32_t* bph = &bh[nt >> 1][(nt & 1) * 2];
                mma_f16(acc[0][nt], ah[0], bph);
                mma_f16(acc[1][nt], ah[1], bph);
            }
            #pragma unroll
            for (int nt = 0; nt < 8; nt++) {
                const uint32_t* bpl = &blo[nt >> 1][(nt & 1) * 2];
                mma_f16(acc[0][nt], ah[0], bpl);
                mma_f16(acc[1][nt], ah[1], bpl);
            }
            if (TERMS == 3) {
                #pragma unroll
                for (int nt = 0; nt < 8; nt++) {
                    const uint32_t* bph = &bh[nt >> 1][(nt & 1) * 2];
                    mma_f16(acc[0][nt], alo[0], bph);
                    mma_f16(acc[1][nt], alo[1], bph);
                }
            }
        }
    }

    // ---- epilogue ----
    #pragma unroll
    for (int nt = 0; nt < 8; nt++) {
        const long long ccol = n0 + wn * 64 + nt * 8 + tg * 2;
        const float b0 = bias ? bias[ccol]     : 0.0f;
        const float b1 = bias ? bias[ccol + 1] : 0.0f;
        #pragma unroll
        for (int mt = 0; mt < 2; mt++) {
            const long long rA = m0 + wm * 32 + mt * 16 + g;
            const long long rB = rA + 8;
            const float f0 = acc[mt][nt][0] * scale + b0;
            const float f1 = acc[mt][nt][1] * scale + b1;
            const float f2 = acc[mt][nt][2] * scale + b0;
            const float f3 = acc[mt][nt][3] * scale + b1;
            if (MODE == 0) {
                *(float2*)(Cf + zC + rA * ldC + ccol) = make_float2(f0, f1);
                *(float2*)(Cf + zC + rB * ldC + ccol) = make_float2(f2, f3);
            } else {
                uint32_t h, l;
                split2(f0, f1, h, l);
                *(uint32_t*)(Ch + zC + rA * ldC + ccol) = h;
                if (MODE == 1) *(uint32_t*)(Cl + zC + rA * ldC + ccol) = l;
                split2(f2, f3, h, l);
                *(uint32_t*)(Ch + zC + rB * ldC + ccol) = h;
                if (MODE == 1) *(uint32_t*)(Cl + zC + rB * ldC + ccol) = l;
            }
        }
    }
}

// ---------------------------------------------------------------------------
// Fused split of q, k, v (z selects tensor)
// ---------------------------------------------------------------------------
__global__ void __launch_bounds__(256)
split_qkv(const float* __restrict__ q, const float* __restrict__ k,
          const float* __restrict__ v,
          __half* __restrict__ qh, __half* __restrict__ ql,
          __half* __restrict__ kh, __half* __restrict__ kl,
          __half* __restrict__ vh, __half* __restrict__ vl, int n4)
{
    const int i = blockIdx.x * 256 + threadIdx.x;
    if (i >= n4) return;
    const int z = blockIdx.y;
    const float* in = (z == 0) ? q : (z == 1) ? k : v;
    __half* oh = (z == 0) ? qh : (z == 1) ? kh : vh;
    __half* ol = (z == 0) ? ql : (z == 1) ? kl : vl;
    float4 f = ((const float4*)in)[i];
    uint32_t h0, l0, h1, l1;
    split2(f.x, f.y, h0, l0);
    split2(f.z, f.w, h1, l1);
    ((uint32_t*)oh)[2 * i]     = h0;
    ((uint32_t*)oh)[2 * i + 1] = h1;
    ((uint32_t*)ol)[2 * i]     = l0;
    ((uint32_t*)ol)[2 * i + 1] = l1;
}

// ---------------------------------------------------------------------------
// Fused transpose+split of the four 512x512 weights (z selects weight)
// ---------------------------------------------------------------------------
__global__ void __launch_bounds__(256)
transpose_w4(const float* __restrict__ w0, const float* __restrict__ w1,
             const float* __restrict__ w2, const float* __restrict__ w3,
             __half* __restrict__ h0p, __half* __restrict__ l0p,
             __half* __restrict__ h1p, __half* __restrict__ l1p,
             __half* __restrict__ h2p, __half* __restrict__ l2p,
             __half* __restrict__ h3p, __half* __restrict__ l3p)
{
    __shared__ float t[32][33];
    const int z = blockIdx.z;
    const float* in = (z == 0) ? w0 : (z == 1) ? w1 : (z == 2) ? w2 : w3;
    __half* oh = (z == 0) ? h0p : (z == 1) ? h1p : (z == 2) ? h2p : h3p;
    __half* ol = (z == 0) ? l0p : (z == 1) ? l1p : (z == 2) ? l2p : l3p;
    const int tx = threadIdx.x, ty = threadIdx.y;
    const int c0 = blockIdx.x * 32, r0 = blockIdx.y * 32;
    #pragma unroll
    for (int i = ty; i < 32; i += 8)
        t[i][tx] = in[(r0 + i) * 512 + c0 + tx];
    __syncthreads();
    #pragma unroll
    for (int i = ty; i < 32; i += 8) {
        const int idx = (c0 + i) * 512 + r0 + tx;
        const float x = t[tx][i];
        const __half h = __float2half_rn(x);
        oh[idx] = h;
        ol[idx] = __float2half_rn(x - __half2float(h));
    }
}

// ---------------------------------------------------------------------------
// Transpose + split (vp -> vT planes)
// ---------------------------------------------------------------------------
__global__ void __launch_bounds__(256)
transpose_split(const float* __restrict__ in, __half* __restrict__ oh,
                __half* __restrict__ ol, int rows, int cols,
                long long sIn, long long sOut)
{
    __shared__ float t[32][33];
    in += (long long)blockIdx.z * sIn;
    const int tx = threadIdx.x, ty = threadIdx.y;
    const int c0 = blockIdx.x * 32, r0 = blockIdx.y * 32;
    #pragma unroll
    for (int i = ty; i < 32; i += 8)
        t[i][tx] = in[(long long)(r0 + i) * cols + c0 + tx];
    __syncthreads();
    #pragma unroll
    for (int i = ty; i < 32; i += 8) {
        const long long idx = (long long)blockIdx.z * sOut + (long long)(c0 + i) * rows + r0 + tx;
        const float x = t[tx][i];
        const __half h = __float2half_rn(x);
        oh[idx] = h;
        ol[idx] = __float2half_rn(x - __half2float(h));
    }
}

// ---------------------------------------------------------------------------
// Row softmax: read S fp32, write P hi plane only
// ---------------------------------------------------------------------------
__global__ void __launch_bounds__(256)
softmax_kernel(const float* __restrict__ S, __half* __restrict__ Ph)
{
    const int row = blockIdx.x;
    const float4* p4 = (const float4*)(S + (size_t)row * SEQ);
    const int tid = threadIdx.x;

    float4 v[4];
    float m = -1e30f;
    #pragma unroll
    for (int i = 0; i < 4; i++) {
        v[i] = p4[tid + i * 256];
        m = fmaxf(m, fmaxf(fmaxf(v[i].x, v[i].y), fmaxf(v[i].z, v[i].w)));
    }

    __shared__ float red[8];
    #pragma unroll
    for (int o = 16; o > 0; o >>= 1) m = fmaxf(m, __shfl_xor_sync(0xffffffffu, m, o));
    if ((tid & 31) == 0) red[tid >> 5] = m;
    __syncthreads();
    if (tid == 0) {
        float t = red[0];
        #pragma unroll
        for (int w = 1; w < 8; w++) t = fmaxf(t, red[w]);
        red[0] = t;
    }
    __syncthreads();
    m = red[0];
    __syncthreads();

    float s = 0.0f;
    #pragma unroll
    for (int i = 0; i < 4; i++) {
        v[i].x = __expf(v[i].x - m);  s += v[i].x;
        v[i].y = __expf(v[i].y - m);  s += v[i].y;
        v[i].z = __expf(v[i].z - m);  s += v[i].z;
        v[i].w = __expf(v[i].w - m);  s += v[i].w;
    }
    #pragma unroll
    for (int o = 16; o > 0; o >>= 1) s += __shfl_xor_sync(0xffffffffu, s, o);
    if ((tid & 31) == 0) red[tid >> 5] = s;
    __syncthreads();
    if (tid == 0) {
        float t = 0.0f;
        #pragma unroll
        for (int w = 0; w < 8; w++) t += red[w];
        red[0] = t;
    }
    __syncthreads();
    const float inv = 1.0f / red[0];

    uint32_t* ph = (uint32_t*)(Ph + (size_t)row * SEQ);
    #pragma unroll
    for (int i = 0; i < 4; i++) {
        const int e = tid + i * 256;
        __half2 a = __floats2half2_rn(v[i].x * inv, v[i].y * inv);
        __half2 b = __floats2half2_rn(v[i].z * inv, v[i].w * inv);
        ph[2 * e]     = *(uint32_t*)&a;
        ph[2 * e + 1] = *(uint32_t*)&b;
    }
}

// ---------------------------------------------------------------------------
// Launch.  Order chosen so launch #5 (ncu capture point) = S GEMM.
// ---------------------------------------------------------------------------
extern "C" void kernel_launch(void* const* d_in, const int* in_sizes, int n_in,
                              void* d_out, int out_size)
{
    const float* q     = (const float*)d_in[0];
    const float* k     = (const float*)d_in[1];
    const float* v     = (const float*)d_in[2];
    const float* w_q   = (const float*)d_in[3];
    const float* w_k   = (const float*)d_in[4];
    const float* w_v   = (const float*)d_in[5];
    const float* w_mha = (const float*)d_in[6];
    const float* b_q   = (const float*)d_in[7];
    const float* b_k   = (const float*)d_in[8];
    const float* b_v   = (const float*)d_in[9];
    const float* b_mha = (const float*)d_in[10];
    float* out = (float*)d_out;

    __half *qh,*ql,*kh,*kl,*vh,*vl, *wqh,*wql,*wkh,*wkl,*wvh,*wvl,*wmh,*wml;
    __half *qph,*qpl,*kph,*kpl,*vTh,*vTl,*Ph,*dh;
    float *vp, *S;
    cudaGetSymbolAddress((void**)&qh,  g_qh);  cudaGetSymbolAddress((void**)&ql,  g_ql);
    cudaGetSymbolAddress((void**)&kh,  g_kh);  cudaGetSymbolAddress((void**)&kl,  g_kl);
    cudaGetSymbolAddress((void**)&vh,  g_vh);  cudaGetSymbolAddress((void**)&vl,  g_vl);
    cudaGetSymbolAddress((void**)&wqh, g_wqh); cudaGetSymbolAddress((void**)&wql, g_wql);
    cudaGetSymbolAddress((void**)&wkh, g_wkh); cudaGetSymbolAddress((void**)&wkl, g_wkl);
    cudaGetSymbolAddress((void**)&wvh, g_wvh); cudaGetSymbolAddress((void**)&wvl, g_wvl);
    cudaGetSymbolAddress((void**)&wmh, g_wmh); cudaGetSymbolAddress((void**)&wml, g_wml);
    cudaGetSymbolAddress((void**)&qph, g_qph); cudaGetSymbolAddress((void**)&qpl, g_qpl);
    cudaGetSymbolAddress((void**)&kph, g_kph); cudaGetSymbolAddress((void**)&kpl, g_kpl);
    cudaGetSymbolAddress((void**)&vTh, g_vTh); cudaGetSymbolAddress((void**)&vTl, g_vTl);
    cudaGetSymbolAddress((void**)&Ph,  g_Ph);
    cudaGetSymbolAddress((void**)&dh,  g_dh);
    cudaGetSymbolAddress((void**)&vp,  g_vp);  cudaGetSymbolAddress((void**)&S,   g_S);

    const long long sP = (long long)SEQ * PROJD;
    const long long sS = (long long)SEQ * SEQ;

    cudaFuncSetAttribute(gemm16<0,3>, cudaFuncAttributeMaxDynamicSharedMemorySize, SMEM_TOTAL);
    cudaFuncSetAttribute(gemm16<1,3>, cudaFuncAttributeMaxDynamicSharedMemorySize, SMEM_TOTAL);
    cudaFuncSetAttribute(gemm16<2,2>, cudaFuncAttributeMaxDynamicSharedMemorySize, SMEM_TOTAL);
    cudaFuncSetAttribute(gemm16<0,2>, cudaFuncAttributeMaxDynamicSharedMemorySize, SMEM_TOTAL);

    dim3 tblk(32, 8);

    // #0: split q,k,v
    const int n4 = MFLAT * DMODEL / 4;
    split_qkv<<<dim3(n4 / 256, 3), 256>>>(q, k, v, qh, ql, kh, kl, vh, vl, n4);
    // #1: transpose+split all 4 weights
    transpose_w4<<<dim3(16, 16, 4), tblk>>>(w_q, w_k, w_v, w_mha,
                                            wqh, wql, wkh, wkl, wvh, wvl, wmh, wml);
    // #2-#4: projections
    {
        dim3 grd(PROJD / 128, MFLAT / 128, 1);
        gemm16<1,3><<<grd, 256, SMEM_TOTAL>>>(qh, ql, wqh, wql, nullptr, qph, qpl,
                                              b_q, 1.0f, DMODEL, PROJD, 0, 0, 0);
        gemm16<1,3><<<grd, 256, SMEM_TOTAL>>>(kh, kl, wkh, wkl, nullptr, kph, kpl,
                                              b_k, 1.0f, DMODEL, PROJD, 0, 0, 0);
        gemm16<0,3><<<grd, 256, SMEM_TOTAL>>>(vh, vl, wvh, wvl, vp, nullptr, nullptr,
                                              b_v, 1.0f, DMODEL, PROJD, 0, 0, 0);
    }
    // #5: S = 0.125 * qp @ kp^T  (ncu capture lands here)
    gemm16<0,3><<<dim3(SEQ / 128, SEQ / 128, BATCH), 256, SMEM_TOTAL>>>(
        qph, qpl, kph, kpl, S, nullptr, nullptr, nullptr, SCALE_QK,
        PROJD, SEQ, sP, sP, sS);
    // #6: vp -> vT planes
    transpose_split<<<dim3(16, 128, BATCH), tblk>>>(vp, vTh, vTl, SEQ, PROJD, sP, sP);
    // #7: softmax -> Ph (hi only)
    softmax_kernel<<<BATCH * SEQ, 256>>>(S, Ph);
    // #8: dpa = P @ vT^T  (A hi-only; write dh only)
    gemm16<2,2><<<dim3(PROJD / 128, SEQ / 128, BATCH), 256, SMEM_TOTAL>>>(
        Ph, nullptr, vTh, vTl, nullptr, dh, nullptr, nullptr, 1.0f,
        SEQ, PROJD, sS, sP, sP);
    // #9: out = dpa @ wm^T + b_mha  (A hi-only)
    gemm16<0,2><<<dim3(DMODEL / 128, MFLAT / 128, 1), 256, SMEM_TOTAL>>>(
        dh, nullptr, wmh, wml, out, nullptr, nullptr, b_mha, 1.0f,
        PROJD, DMODEL, 0, 0, 0);
}